// round 6
// baseline (speedup 1.0000x reference)
#include <cuda_runtime.h>
#include <cuda_bf16.h>
#include <cstdint>
#include <cstddef>

// ---------------- problem constants ----------------
#define Bv   128
#define Nv   196
#define Lv   25
#define Tv   24
#define Vv   10000
#define Ev   300
#define Av   512
#define ENCv 512
#define Dv   512
#define G4D  2048   // 4*D
#define KE   320    // E padded to multiple of 32
#define VP   10112  // V padded to multiple of 64
#define XK   1024   // K of gates GEMM: [ctx | h]

// ---------------- device scratch (static, no allocation) ----------------
__device__ float g_featproj[(size_t)Bv * Nv * Av];      // [B*N, A]
__device__ float g_embgates[(size_t)Tv * Bv * G4D];     // [T*B, 2048] interleaved-gate
__device__ float g_bias2i[G4D];                         // interleaved b_ih+b_hh
__device__ float g_meanf[Bv * ENCv];
__device__ float g_h0[Bv * Dv];
__device__ float g_c[Bv * Dv];
__device__ float g_dec[Bv * Av];

// bf16 hi/lo operand buffers (A row-major [M,K]; B as Bt row-major [N,K])
__device__ __nv_bfloat16 g_feat_hi[(size_t)Bv * Nv * ENCv];
__device__ __nv_bfloat16 g_feat_lo[(size_t)Bv * Nv * ENCv];
__device__ __nv_bfloat16 g_WencT_hi[Av * ENCv];
__device__ __nv_bfloat16 g_WencT_lo[Av * ENCv];
__device__ __nv_bfloat16 g_WdecT_hi[Av * Dv];
__device__ __nv_bfloat16 g_WdecT_lo[Av * Dv];
__device__ __nv_bfloat16 g_WihTi_hi[G4D * KE];           // interleaved rows, K=320
__device__ __nv_bfloat16 g_WihTi_lo[G4D * KE];
__device__ __nv_bfloat16 g_WcatTi_hi[(size_t)G4D * XK];  // interleaved rows, K=1024
__device__ __nv_bfloat16 g_WcatTi_lo[(size_t)G4D * XK];
__device__ __nv_bfloat16 g_WoutT_hi[(size_t)VP * Dv];
__device__ __nv_bfloat16 g_WoutT_lo[(size_t)VP * Dv];
__device__ __nv_bfloat16 g_embA_hi[Tv * Bv * KE];
__device__ __nv_bfloat16 g_embA_lo[Tv * Bv * KE];
__device__ __nv_bfloat16 g_H_hi[(size_t)Tv * Bv * Dv];
__device__ __nv_bfloat16 g_H_lo[(size_t)Tv * Bv * Dv];
__device__ __nv_bfloat16 g_x_hi[2 * Bv * XK];            // ping-pong [ctx | h]
__device__ __nv_bfloat16 g_x_lo[2 * Bv * XK];

// ---------------- PTX helpers ----------------
__device__ __forceinline__ uint32_t smem_u32(const void* p) {
    uint32_t a;
    asm("{ .reg .u64 t; cvta.to.shared.u64 t, %1; cvt.u32.u64 %0, t; }" : "=r"(a) : "l"(p));
    return a;
}

#define LDSM4(r, addr) \
    asm volatile("ldmatrix.sync.aligned.m8n8.x4.shared.b16 {%0,%1,%2,%3}, [%4];" \
        : "=r"((r)[0]), "=r"((r)[1]), "=r"((r)[2]), "=r"((r)[3]) : "r"(addr))

#define MMA16816(d, a, b0, b1) \
    asm volatile("mma.sync.aligned.m16n8k16.row.col.f32.bf16.bf16.f32 " \
        "{%0,%1,%2,%3}, {%4,%5,%6,%7}, {%8,%9}, {%0,%1,%2,%3};" \
        : "+f"((d)[0]), "+f"((d)[1]), "+f"((d)[2]), "+f"((d)[3]) \
        : "r"((a)[0]), "r"((a)[1]), "r"((a)[2]), "r"((a)[3]), "r"(b0), "r"(b1))

#define CP16(dst, src) \
    asm volatile("cp.async.cg.shared.global [%0], [%1], 16;" :: "r"(dst), "l"(src) : "memory")
#define CP_COMMIT() asm volatile("cp.async.commit_group;" ::: "memory")
#define CP_WAIT1() asm volatile("cp.async.wait_group 1;" ::: "memory")
#define CP_WAIT0() asm volatile("cp.async.wait_group 0;" ::: "memory")

// =================================================================
// Shared HMMA mainloop: CTA tile 128x64, BK=32, 2-stage cp.async pipeline.
// smem row stride 80 B (conflict-free for ldmatrix and cp.async stores).
// =================================================================
#define SS      30720       // stage stride bytes
#define OFF_AHI 0
#define OFF_ALO 10240
#define OFF_BHI 20480
#define OFF_BLO 25600
#define HM_SMEM (2 * SS)    // 61440

__device__ __forceinline__ void load_stage(
    uint32_t base,
    const __nv_bfloat16* __restrict__ Ahi, const __nv_bfloat16* __restrict__ Alo, int lda,
    const __nv_bfloat16* __restrict__ Bhi, const __nv_bfloat16* __restrict__ Blo, int ldb,
    int row0, int col0, int koff, int tid)
{
#pragma unroll
    for (int i = 0; i < 2; i++) {
        int idx = tid + i * 256;
        int r = idx >> 2, seg = idx & 3;
        uint32_t d = base + (uint32_t)(r * 80 + seg * 16);
        const __nv_bfloat16* pa = Ahi + (size_t)(row0 + r) * lda + koff + seg * 8;
        const __nv_bfloat16* pl = Alo + (size_t)(row0 + r) * lda + koff + seg * 8;
        CP16(d + OFF_AHI, pa);
        CP16(d + OFF_ALO, pl);
    }
    {
        int r = tid >> 2, seg = tid & 3;
        uint32_t d = base + (uint32_t)(r * 80 + seg * 16);
        const __nv_bfloat16* pb = Bhi + (size_t)(col0 + r) * ldb + koff + seg * 8;
        const __nv_bfloat16* pl = Blo + (size_t)(col0 + r) * ldb + koff + seg * 8;
        CP16(d + OFF_BHI, pb);
        CP16(d + OFF_BLO, pl);
    }
}

__device__ __forceinline__ void compute_stage(
    uint32_t sbase, int warp_m, int warp_n, int lane, float acc[4][2][4])
{
    const int a_lr = lane & 15, a_lk = (lane >> 4) * 8;
    const int b_grp = lane >> 3;
    const int b_lr = (lane & 7) + ((b_grp >> 1) * 8);
    const int b_lk = (b_grp & 1) * 8;
#pragma unroll
    for (int k16 = 0; k16 < 32; k16 += 16) {
        uint32_t aHi[4][4], aLo[4][4], bH[4], bL[4];
#pragma unroll
        for (int mt = 0; mt < 4; mt++) {
            uint32_t ab = sbase + (uint32_t)((warp_m * 64 + mt * 16 + a_lr) * 80
                                             + (k16 + a_lk) * 2);
            LDSM4(aHi[mt], ab + OFF_AHI);
            LDSM4(aLo[mt], ab + OFF_ALO);
        }
        uint32_t bb = sbase + (uint32_t)((warp_n * 16 + b_lr) * 80 + (k16 + b_lk) * 2);
        LDSM4(bH, bb + OFF_BHI);
        LDSM4(bL, bb + OFF_BLO);
#pragma unroll
        for (int mt = 0; mt < 4; mt++)
#pragma unroll
            for (int nt = 0; nt < 2; nt++) {
                MMA16816(acc[mt][nt], aHi[mt], bH[nt * 2], bH[nt * 2 + 1]);
                MMA16816(acc[mt][nt], aLo[mt], bH[nt * 2], bH[nt * 2 + 1]);
                MMA16816(acc[mt][nt], aHi[mt], bL[nt * 2], bL[nt * 2 + 1]);
            }
    }
}

__device__ __forceinline__ void hmma_mainloop(
    uint32_t sb,
    const __nv_bfloat16* __restrict__ Ahi, const __nv_bfloat16* __restrict__ Alo, int lda,
    const __nv_bfloat16* __restrict__ Bhi, const __nv_bfloat16* __restrict__ Blo, int ldb,
    int row0, int col0, int K, int tid, int warp_m, int warp_n, int lane,
    float acc[4][2][4])
{
    const int nch = K >> 5;
    load_stage(sb, Ahi, Alo, lda, Bhi, Blo, ldb, row0, col0, 0, tid);
    CP_COMMIT();
    for (int kc = 0; kc < nch; kc++) {
        if (kc + 1 < nch) {
            load_stage(sb + (uint32_t)(((kc + 1) & 1) * SS), Ahi, Alo, lda,
                       Bhi, Blo, ldb, row0, col0, (kc + 1) * 32, tid);
            CP_COMMIT();
            CP_WAIT1();
        } else {
            CP_WAIT0();
        }
        __syncthreads();
        compute_stage(sb + (uint32_t)((kc & 1) * SS), warp_m, warp_n, lane, acc);
        __syncthreads();
    }
}

// =================================================================
// Generic HMMA GEMM: C = A @ Bt^T + bias  (remap=1: row t*128+b -> b*Tv+t)
// =================================================================
__global__ __launch_bounds__(256, 2)
void hmma_kernel(int Nreal, int K,
                 const __nv_bfloat16* __restrict__ Ahi, const __nv_bfloat16* __restrict__ Alo, int lda,
                 const __nv_bfloat16* __restrict__ Bhi, const __nv_bfloat16* __restrict__ Blo, int ldb,
                 float* __restrict__ C, int ldc,
                 const float* __restrict__ bias, int remap)
{
    extern __shared__ char smc[];
    const uint32_t sb = smem_u32(smc);
    const int tid = threadIdx.x, wid = tid >> 5, lane = tid & 31;
    const int warp_m = wid & 1, warp_n = wid >> 1;
    const int row0 = blockIdx.y * 128, col0 = blockIdx.x * 64;

    float acc[4][2][4];
#pragma unroll
    for (int a = 0; a < 4; a++)
#pragma unroll
        for (int b = 0; b < 2; b++)
#pragma unroll
            for (int r = 0; r < 4; r++) acc[a][b][r] = 0.f;

    hmma_mainloop(sb, Ahi, Alo, lda, Bhi, Blo, ldb, row0, col0, K,
                  tid, warp_m, warp_n, lane, acc);

    const int quad = lane >> 2, tc = lane & 3;
#pragma unroll
    for (int mt = 0; mt < 4; mt++)
#pragma unroll
        for (int half = 0; half < 2; half++) {
            const int gm = row0 + warp_m * 64 + mt * 16 + quad + half * 8;
            const size_t rowC = remap ? ((size_t)(gm & (Bv - 1)) * Tv + (gm >> 7))
                                      : (size_t)gm;
#pragma unroll
            for (int nt = 0; nt < 2; nt++) {
                const int gn = col0 + warp_n * 16 + nt * 8 + tc * 2;
                if (gn >= Nreal) continue;
                const float2 bv = *(const float2*)&bias[gn];
                float2 o;
                o.x = acc[mt][nt][half * 2]     + bv.x;
                o.y = acc[mt][nt][half * 2 + 1] + bv.y;
                *(float2*)&C[rowC * (size_t)ldc + gn] = o;
            }
        }
}

// =================================================================
// Gates GEMM + fused LSTM epilogue. grid = (32,1). Interleaved gates.
// gates = x @ WcatTi^T + embgates_int[t];  then LSTM pointwise.
// =================================================================
__global__ __launch_bounds__(256, 2)
void gates_kernel(const __nv_bfloat16* __restrict__ xHi, const __nv_bfloat16* __restrict__ xLo,
                  const __nv_bfloat16* __restrict__ wHi, const __nv_bfloat16* __restrict__ wLo,
                  const float* __restrict__ egt,      // embgates + t*Bv*G4D
                  float* __restrict__ c,
                  __nv_bfloat16* __restrict__ xnHi, __nv_bfloat16* __restrict__ xnLo,
                  __nv_bfloat16* __restrict__ HtHi, __nv_bfloat16* __restrict__ HtLo)
{
    extern __shared__ char smc[];
    const uint32_t sb = smem_u32(smc);
    const int tid = threadIdx.x, wid = tid >> 5, lane = tid & 31;
    const int warp_m = wid & 1, warp_n = wid >> 1;
    const int col0 = blockIdx.x * 64;

    float acc[4][2][4];
#pragma unroll
    for (int a = 0; a < 4; a++)
#pragma unroll
        for (int b = 0; b < 2; b++)
#pragma unroll
            for (int r = 0; r < 4; r++) acc[a][b][r] = 0.f;

    hmma_mainloop(sb, xHi, xLo, XK, wHi, wLo, XK, 0, col0, XK,
                  tid, warp_m, warp_n, lane, acc);

    // stage gates (plus embgates) into smem f32 [128][68]
    float* gs = (float*)smc;
    const int quad = lane >> 2, tc = lane & 3;
#pragma unroll
    for (int mt = 0; mt < 4; mt++)
#pragma unroll
        for (int half = 0; half < 2; half++) {
            const int gm = warp_m * 64 + mt * 16 + quad + half * 8;
#pragma unroll
            for (int nt = 0; nt < 2; nt++) {
                const int gn = warp_n * 16 + nt * 8 + tc * 2;
                const float2 e = *(const float2*)&egt[(size_t)gm * G4D + col0 + gn];
                gs[gm * 68 + gn]     = acc[mt][nt][half * 2]     + e.x;
                gs[gm * 68 + gn + 1] = acc[mt][nt][half * 2 + 1] + e.y;
            }
        }
    __syncthreads();

    const int d0 = col0 >> 2;
#pragma unroll
    for (int i = tid; i < 2048; i += 256) {
        const int b = i >> 4, u = i & 15;
        const float* gr = gs + b * 68 + u * 4;
        const float gi = gr[0], gf = gr[1], gg = gr[2], go = gr[3];
        const int d = d0 + u;
        const float si = 1.f / (1.f + __expf(-gi));
        const float sf = 1.f / (1.f + __expf(-gf));
        const float so = 1.f / (1.f + __expf(-go));
        const float tg = tanhf(gg);
        const float cn = sf * c[b * Dv + d] + si * tg;
        c[b * Dv + d] = cn;
        const float h = so * tanhf(cn);
        const __nv_bfloat16 hh = __float2bfloat16(h);
        const __nv_bfloat16 hl = __float2bfloat16(h - __bfloat162float(hh));
        xnHi[b * XK + Dv + d] = hh;
        xnLo[b * XK + Dv + d] = hl;
        HtHi[b * Dv + d] = hh;
        HtLo[b * Dv + d] = hl;
    }
}

// =================================================================
// Small fp32 SGEMM (one-time h0/c0 init only)
// =================================================================
template<int BM, int BN, int BK, int TM, int TN>
__global__ void sgemm_kernel(int M, int N, int K,
                             const float* __restrict__ A, int lda,
                             const float* __restrict__ B, int ldb,
                             float* __restrict__ C, int ldc,
                             const float* __restrict__ bias)
{
    constexpr int TX = BN / TN;
    constexpr int TY = BM / TM;
    constexpr int NT = TX * TY;
    __shared__ float As[BK][BM + 1];
    __shared__ float Bs[BK][BN];

    const int tid = threadIdx.x;
    const int tx = tid % TX, ty = tid / TX;
    const int row0 = blockIdx.y * BM;
    const int col0 = blockIdx.x * BN;

    float acc[TM][TN];
#pragma unroll
    for (int i = 0; i < TM; i++)
#pragma unroll
        for (int j = 0; j < TN; j++) acc[i][j] = 0.f;

    for (int k0 = 0; k0 < K; k0 += BK) {
#pragma unroll
        for (int i = tid; i < BM * BK; i += NT) {
            int m = i / BK, k = i % BK;
            As[k][m] = A[(size_t)(row0 + m) * lda + k0 + k];
        }
#pragma unroll
        for (int i = tid; i < BK * BN; i += NT) {
            int k = i / BN, n = i % BN;
            Bs[k][n] = B[(size_t)(k0 + k) * ldb + col0 + n];
        }
        __syncthreads();
#pragma unroll
        for (int kk = 0; kk < BK; kk++) {
            float ra[TM], rb[TN];
#pragma unroll
            for (int i = 0; i < TM; i++) ra[i] = As[kk][ty * TM + i];
#pragma unroll
            for (int j = 0; j < TN; j++) rb[j] = Bs[kk][tx * TN + j];
#pragma unroll
            for (int i = 0; i < TM; i++)
#pragma unroll
                for (int j = 0; j < TN; j++)
                    acc[i][j] = fmaf(ra[i], rb[j], acc[i][j]);
        }
        __syncthreads();
    }

#pragma unroll
    for (int i = 0; i < TM; i++)
#pragma unroll
        for (int j = 0; j < TN; j++) {
            int gm = row0 + ty * TM + i, gn = col0 + tx * TN + j;
            C[(size_t)gm * ldc + gn] = acc[i][j] + bias[gn];
        }
}

// ---------------- prep kernels ----------------
__device__ __forceinline__ void split_hilo(float v, __nv_bfloat16& h, __nv_bfloat16& l) {
    h = __float2bfloat16(v);
    l = __float2bfloat16(v - __bfloat162float(h));
}

// WcatTi[n, k]: k<512 -> W_ih[E+k, col_old], else W_hh[k-512, col_old]
__global__ void wcatTi_kernel(const float* __restrict__ Wih, const float* __restrict__ Whh,
                              __nv_bfloat16* __restrict__ hi, __nv_bfloat16* __restrict__ lo)
{
    int idx = blockIdx.x * blockDim.x + threadIdx.x;
    if (idx >= G4D * XK) return;
    int k = idx & (XK - 1), n = idx >> 10;
    int col_old = (n & 3) * 512 + (n >> 2);
    float v = (k < 512) ? Wih[(size_t)(Ev + k) * G4D + col_old]
                        : Whh[(size_t)(k - 512) * G4D + col_old];
    split_hilo(v, hi[idx], lo[idx]);
}

// WihTi[n, k] (k in [0,320), zero-padded past 300), interleaved rows
__global__ void wihTi_kernel(const float* __restrict__ Wih,
                             __nv_bfloat16* __restrict__ hi, __nv_bfloat16* __restrict__ lo)
{
    int idx = blockIdx.x * blockDim.x + threadIdx.x;
    if (idx >= G4D * KE) return;
    int k = idx % KE, n = idx / KE;
    int col_old = (n & 3) * 512 + (n >> 2);
    float v = (k < Ev) ? Wih[(size_t)k * G4D + col_old] : 0.f;
    split_hilo(v, hi[idx], lo[idx]);
}

__global__ void bias2i_kernel(const float* __restrict__ bih, const float* __restrict__ bhh,
                              float* __restrict__ b2)
{
    int n = blockIdx.x * blockDim.x + threadIdx.x;
    if (n >= G4D) return;
    int col_old = (n & 3) * 512 + (n >> 2);
    b2[n] = bih[col_old] + bhh[col_old];
}

__global__ void embgather_hilo_kernel(const float* __restrict__ emb, const int* __restrict__ cap,
                                      __nv_bfloat16* __restrict__ hi, __nv_bfloat16* __restrict__ lo)
{
    int idx = blockIdx.x * blockDim.x + threadIdx.x;
    if (idx >= Tv * Bv * KE) return;
    int k = idx % KE, r = idx / KE;
    int t = r / Bv, b = r % Bv;
    float v = 0.f;
    if (k < Ev) v = emb[(size_t)cap[b * Lv + t] * Ev + k];
    split_hilo(v, hi[idx], lo[idx]);
}

// vectorized fp32 -> hi/lo (n divisible by 4)
__global__ void conv4_hilo_kernel(const float4* __restrict__ in, size_t n4,
                                  __nv_bfloat162* __restrict__ hi, __nv_bfloat162* __restrict__ lo)
{
    size_t idx = (size_t)blockIdx.x * blockDim.x + threadIdx.x;
    if (idx >= n4) return;
    float4 v = in[idx];
    __nv_bfloat16 h0, l0, h1, l1, h2, l2, h3, l3;
    split_hilo(v.x, h0, l0); split_hilo(v.y, h1, l1);
    split_hilo(v.z, h2, l2); split_hilo(v.w, h3, l3);
    hi[idx * 2]     = __nv_bfloat162(h0, h1);
    hi[idx * 2 + 1] = __nv_bfloat162(h2, h3);
    lo[idx * 2]     = __nv_bfloat162(l0, l1);
    lo[idx * 2 + 1] = __nv_bfloat162(l2, l3);
}

// transpose fp32 [R,C] -> hi/lo bf16 [Npad, Kpad]: out[n,k] = in[k,n], zero pad
__global__ void trans_hilo_kernel(const float* __restrict__ in, int R, int C,
                                  __nv_bfloat16* __restrict__ hi, __nv_bfloat16* __restrict__ lo,
                                  int Kpad, int Npad)
{
    __shared__ float t[32][33];
    const int cb = blockIdx.x * 32;
    const int rb = blockIdx.y * 32;
    const int x = threadIdx.x, y = threadIdx.y;
#pragma unroll
    for (int i = y; i < 32; i += 8) {
        int r = rb + i, ccol = cb + x;
        t[i][x] = (r < R && ccol < C) ? in[(size_t)r * C + ccol] : 0.f;
    }
    __syncthreads();
#pragma unroll
    for (int i = y; i < 32; i += 8) {
        int n = cb + i, k = rb + x;
        if (n < Npad && k < Kpad) {
            size_t o = (size_t)n * Kpad + k;
            split_hilo(t[x][i], hi[o], lo[o]);
        }
    }
}

__global__ void meanf_kernel(const float* __restrict__ feat, float* __restrict__ mf)
{
    int b = blockIdx.x, tid = threadIdx.x;
    for (int d = tid; d < ENCv; d += 256) {
        float s = 0.f;
        const float* p = feat + (size_t)b * Nv * ENCv + d;
#pragma unroll 4
        for (int n = 0; n < Nv; n++) s += p[(size_t)n * ENCv];
        mf[b * ENCv + d] = s * (1.0f / (float)Nv);
    }
}

// h0 fp32 -> hi/lo into x buffer's h slot
__global__ void h0x_kernel(const float* __restrict__ h0,
                           __nv_bfloat16* __restrict__ xHi, __nv_bfloat16* __restrict__ xLo)
{
    int idx = blockIdx.x * blockDim.x + threadIdx.x;
    if (idx >= Bv * Dv) return;
    int b = idx >> 9, d = idx & 511;
    split_hilo(h0[idx], xHi[b * XK + Dv + d], xLo[b * XK + Dv + d]);
}

// ---------------- fused attention ----------------
__global__ void attention_kernel(const float* __restrict__ fp,
                                 const float* __restrict__ feat,
                                 const float* __restrict__ dec,   // [B,512]
                                 const float* __restrict__ watt,
                                 __nv_bfloat16* __restrict__ xHi, // ctx -> x[:, 0:512]
                                 __nv_bfloat16* __restrict__ xLo,
                                 float* __restrict__ alphaOut)
{
    __shared__ float s_dec[Av];
    __shared__ float s_watt[Av];
    __shared__ float s_sc[Nv];
    __shared__ float s_red[8];
    const int b = blockIdx.x, tid = threadIdx.x;

    for (int i = tid; i < Av; i += 256) { s_dec[i] = dec[b * Av + i]; s_watt[i] = watt[i]; }
    __syncthreads();

    const int warp = tid >> 5, lane = tid & 31;
    const float* fpb = fp + (size_t)b * Nv * Av;
    for (int n = warp; n < Nv; n += 8) {
        const float* row = fpb + (size_t)n * Av;
        float s = 0.f;
#pragma unroll 4
        for (int k = lane; k < Av; k += 32) {
            float x = row[k] + s_dec[k];
            float th;
            asm("tanh.approx.f32 %0, %1;" : "=f"(th) : "f"(x));
            s = fmaf(th, s_watt[k], s);
        }
#pragma unroll
        for (int o = 16; o; o >>= 1) s += __shfl_xor_sync(0xffffffffu, s, o);
        if (lane == 0) s_sc[n] = s;
    }
    __syncthreads();

    float m = -1e30f;
    for (int n = tid; n < Nv; n += 256) m = fmaxf(m, s_sc[n]);
#pragma unroll
    for (int o = 16; o; o >>= 1) m = fmaxf(m, __shfl_xor_sync(0xffffffffu, m, o));
    if (lane == 0) s_red[warp] = m;
    __syncthreads();
    if (tid == 0) {
        float mm = s_red[0];
        for (int w = 1; w < 8; w++) mm = fmaxf(mm, s_red[w]);
        s_red[0] = mm;
    }
    __syncthreads();
    m = s_red[0];
    __syncthreads();

    float sum = 0.f;
    for (int n = tid; n < Nv; n += 256) {
        float e = __expf(s_sc[n] - m);
        s_sc[n] = e;
        sum += e;
    }
#pragma unroll
    for (int o = 16; o; o >>= 1) sum += __shfl_xor_sync(0xffffffffu, sum, o);
    if (lane == 0) s_red[warp] = sum;
    __syncthreads();
    if (tid == 0) {
        float ss = 0.f;
        for (int w = 0; w < 8; w++) ss += s_red[w];
        s_red[0] = 1.f / ss;
    }
    __syncthreads();
    const float inv = s_red[0];
    for (int n = tid; n < Nv; n += 256) {
        float a = s_sc[n] * inv;
        s_sc[n] = a;
        alphaOut[(size_t)b * Tv * Nv + n] = a;
    }
    __syncthreads();

    const float* fb = feat + (size_t)b * Nv * ENCv;
    for (int d = tid; d < ENCv; d += 256) {
        float acc = 0.f;
#pragma unroll 4
        for (int n = 0; n < Nv; n++) acc = fmaf(s_sc[n], fb[(size_t)n * ENCv + d], acc);
        split_hilo(acc, xHi[b * XK + d], xLo[b * XK + d]);
    }
}

// ---------------- host helper ----------------
static void launch_hmma(int M, int N, int Nreal, int K,
                        const __nv_bfloat16* Ahi, const __nv_bfloat16* Alo, int lda,
                        const __nv_bfloat16* Bhi, const __nv_bfloat16* Blo, int ldb,
                        float* C, int ldc, const float* bias, int remap)
{
    dim3 grid(N / 64, M / 128);
    hmma_kernel<<<grid, 256, HM_SMEM>>>(Nreal, K, Ahi, Alo, lda, Bhi, Blo, ldb,
                                        C, ldc, bias, remap);
}

extern "C" void kernel_launch(void* const* d_in, const int* in_sizes, int n_in,
                              void* d_out, int out_size)
{
    const float* features  = (const float*)d_in[0];
    const int*   captions  = (const int*)  d_in[1];
    const float* embedding = (const float*)d_in[2];
    const float* W_enc     = (const float*)d_in[3];
    const float* b_enc     = (const float*)d_in[4];
    const float* W_dec     = (const float*)d_in[5];
    const float* b_dec     = (const float*)d_in[6];
    const float* w_att     = (const float*)d_in[7];
    // d_in[8] = b_att : softmax-invariant, unused
    const float* Wi_h      = (const float*)d_in[9];
    const float* bi_h      = (const float*)d_in[10];
    const float* Wi_c      = (const float*)d_in[11];
    const float* bi_c      = (const float*)d_in[12];
    const float* W_ih      = (const float*)d_in[13];
    const float* b_ih      = (const float*)d_in[14];
    const float* W_hh      = (const float*)d_in[15];
    const float* b_hh      = (const float*)d_in[16];
    const float* W_out     = (const float*)d_in[17];
    const float* b_out     = (const float*)d_in[18];
    float* out = (float*)d_out;

    cudaFuncSetAttribute(hmma_kernel,  cudaFuncAttributeMaxDynamicSharedMemorySize, HM_SMEM);
    cudaFuncSetAttribute(gates_kernel, cudaFuncAttributeMaxDynamicSharedMemorySize, HM_SMEM);

    float *featproj, *embgates, *bias2i, *meanf, *h0, *c, *dec;
    __nv_bfloat16 *fhi, *flo, *wenchi, *wenclo, *wdechi, *wdeclo, *wihhi, *wihlo,
                  *wcathi, *wcatlo, *wouthi, *woutlo, *eahi, *ealo, *Hhi, *Hlo, *xhi, *xlo;
    cudaGetSymbolAddress((void**)&featproj, g_featproj);
    cudaGetSymbolAddress((void**)&embgates, g_embgates);
    cudaGetSymbolAddress((void**)&bias2i,   g_bias2i);
    cudaGetSymbolAddress((void**)&meanf,    g_meanf);
    cudaGetSymbolAddress((void**)&h0,       g_h0);
    cudaGetSymbolAddress((void**)&c,        g_c);
    cudaGetSymbolAddress((void**)&dec,      g_dec);
    cudaGetSymbolAddress((void**)&fhi,      g_feat_hi);
    cudaGetSymbolAddress((void**)&flo,      g_feat_lo);
    cudaGetSymbolAddress((void**)&wenchi,   g_WencT_hi);
    cudaGetSymbolAddress((void**)&wenclo,   g_WencT_lo);
    cudaGetSymbolAddress((void**)&wdechi,   g_WdecT_hi);
    cudaGetSymbolAddress((void**)&wdeclo,   g_WdecT_lo);
    cudaGetSymbolAddress((void**)&wihhi,    g_WihTi_hi);
    cudaGetSymbolAddress((void**)&wihlo,    g_WihTi_lo);
    cudaGetSymbolAddress((void**)&wcathi,   g_WcatTi_hi);
    cudaGetSymbolAddress((void**)&wcatlo,   g_WcatTi_lo);
    cudaGetSymbolAddress((void**)&wouthi,   g_WoutT_hi);
    cudaGetSymbolAddress((void**)&woutlo,   g_WoutT_lo);
    cudaGetSymbolAddress((void**)&eahi,     g_embA_hi);
    cudaGetSymbolAddress((void**)&ealo,     g_embA_lo);
    cudaGetSymbolAddress((void**)&Hhi,      g_H_hi);
    cudaGetSymbolAddress((void**)&Hlo,      g_H_lo);
    cudaGetSymbolAddress((void**)&xhi,      g_x_hi);
    cudaGetSymbolAddress((void**)&xlo,      g_x_lo);

    dim3 tthr(32, 8);

    // ---- time-invariant precompute ----
    wcatTi_kernel<<<(G4D * XK + 255) / 256, 256>>>(W_ih, W_hh, wcathi, wcatlo);
    wihTi_kernel<<<(G4D * KE + 255) / 256, 256>>>(W_ih, wihhi, wihlo);
    bias2i_kernel<<<(G4D + 255) / 256, 256>>>(b_ih, b_hh, bias2i);
    embgather_hilo_kernel<<<(Tv * Bv * KE + 255) / 256, 256>>>(embedding, captions, eahi, ealo);
    {
        size_t n4 = (size_t)Bv * Nv * ENCv / 4;
        conv4_hilo_kernel<<<(unsigned)((n4 + 255) / 256), 256>>>(
            (const float4*)features, n4, (__nv_bfloat162*)fhi, (__nv_bfloat162*)flo);
    }
    trans_hilo_kernel<<<dim3(16, 16), tthr>>>(W_enc, ENCv, Av, wenchi, wenclo, ENCv, Av);
    trans_hilo_kernel<<<dim3(16, 16), tthr>>>(W_dec, Dv, Av, wdechi, wdeclo, Dv, Av);
    trans_hilo_kernel<<<dim3((VP + 31) / 32, 16), tthr>>>(W_out, Dv, Vv, wouthi, woutlo, Dv, VP);
    // featproj = features @ W_enc + b_enc
    launch_hmma(Bv * Nv, Av, Av, ENCv, fhi, flo, ENCv, wenchi, wenclo, ENCv,
                featproj, Av, b_enc, 0);
    // embgates_int[T*B, 2048] = embA @ WihTi^T + bias2i
    launch_hmma(Tv * Bv, G4D, G4D, KE, eahi, ealo, KE, wihhi, wihlo, KE,
                embgates, G4D, bias2i, 0);
    meanf_kernel<<<Bv, 256>>>(features, meanf);
    {
        dim3 g(Dv / 64, Bv / 32);
        sgemm_kernel<32, 64, 16, 2, 4><<<g, 256>>>(Bv, Dv, ENCv, meanf, ENCv, Wi_h, Dv, h0, Dv, bi_h);
        sgemm_kernel<32, 64, 16, 2, 4><<<g, 256>>>(Bv, Dv, ENCv, meanf, ENCv, Wi_c, Dv, c, Dv, bi_c);
    }
    h0x_kernel<<<(Bv * Dv + 255) / 256, 256>>>(h0, xhi, xlo);

    const size_t PRED = (size_t)Bv * Tv * Vv;
    const size_t XSZ = (size_t)Bv * XK;

    for (int t = 0; t < Tv; t++) {
        __nv_bfloat16* xcHi = xhi + (t & 1) * XSZ;
        __nv_bfloat16* xcLo = xlo + (t & 1) * XSZ;
        __nv_bfloat16* xnHi = xhi + ((t + 1) & 1) * XSZ;
        __nv_bfloat16* xnLo = xlo + ((t + 1) & 1) * XSZ;
        // dec = h_prev @ W_dec + b_dec    (A = x[:, 512:1024])
        launch_hmma(Bv, Av, Av, Dv, xcHi + Dv, xcLo + Dv, XK, wdechi, wdeclo, Dv,
                    dec, Av, b_dec, 0);
        // attention -> ctx into x[:, 0:512], alphas[:, t, :]
        attention_kernel<<<Bv, 256>>>(featproj, features, dec, w_att,
                                      xcHi, xcLo, out + PRED + (size_t)t * Nv);
        // gates GEMM + fused LSTM -> c, h into next x buffer + H[t]
        gates_kernel<<<32, 256, HM_SMEM>>>(
            xcHi, xcLo, wcathi, wcatlo,
            embgates + (size_t)t * Bv * G4D, c,
            xnHi, xnLo,
            Hhi + (size_t)t * Bv * Dv, Hlo + (size_t)t * Bv * Dv);
    }

    // preds: [T*B, V] = H @ W_out^T + b_out, remapped to [B, T, V]
    launch_hmma(Tv * Bv, VP, Vv, Dv, Hhi, Hlo, Dv, wouthi, woutlo, Dv,
                out, Vv, b_out, 1);
}